// round 7
// baseline (speedup 1.0000x reference)
#include <cuda_runtime.h>
#include <math.h>
#include <stdint.h>

#define NROWS 16384
#define DDIM  256
#define NW    64                   // int32 words per row (DDIM/4)
#define KCB   8192

#define OFF_Q   16384
#define OFF_ST  (16384 + NROWS*DDIM)
#define OFF_SC  (16384 + 2*NROWS*DDIM)

#define SLOTS 64
#define EPSF  2.5e-4f
#define SC_INV 1040384.0f          // 1/sc = 8192*127

#define TM     128
#define TKT    64
#define KSLICE 1024
#define NRB    (NROWS / TM)        // 128
#define NSL    (KCB / KSLICE)      // 8
#define NUNITS (NRB * NSL)         // 1024
#define TILES_PER_UNIT (KSLICE / TKT)  // 16
#define GRID_SCAN 296

// smem word layout (int32 words)
#define AW2   (NW * 132)           // As[64][132] = 8448
#define BW2   (NW * 17)            // one B sub-array [64][17] = 1088
#define BBUF  (4 * BW2)            // 4352 per buffer
#define SMEM_WORDS (AW2 + 2 * BBUF + TM)
#define SMEM_BYTES (SMEM_WORDS * 4)    // 69,632 B

__device__ int    d_xq[NROWS * NW];    // int8x4-packed latents
__device__ int    d_cq[KCB * NW];      // int8x4-packed codebook
__device__ float  d_sx[NROWS];
__device__ int    d_epsi[NROWS];
__device__ float  d_hist[KCB];
__device__ int    d_bidx[NROWS];
__device__ int    d_cnt[NROWS];
__device__ int    d_cand[NROWS * SLOTS];
__device__ double d_sqsum;
__device__ int    d_wq;

// ---------------------------------------------------------------------------
__device__ __forceinline__ int dp4a(int acc, int a, int b) {
    asm("dp4a.s32.s32 %0, %1, %2, %0;" : "+r"(acc) : "r"(a), "r"(b));
    return acc;
}
__device__ __forceinline__ int q8(float v) {
    int q = __float2int_rn(v);
    return max(-127, min(127, q));
}
__device__ __forceinline__ int pack4(int a, int b, int c, int d) {
    return (a & 0xFF) | ((b & 0xFF) << 8) | ((c & 0xFF) << 16) | ((d & 0xFF) << 24);
}

// ---------------------------------------------------------------------------
// Kernel 1: zero accumulators + work queue
// ---------------------------------------------------------------------------
__global__ void k_init() {
    int i = blockIdx.x * 256 + threadIdx.x;
    if (i < KCB)   d_hist[i] = 0.f;
    if (i < NROWS) d_cnt[i]  = 0;
    if (i == 0)  { d_sqsum   = 0.0; d_wq = 0; }
}

// ---------------------------------------------------------------------------
// Kernel 2a: quantize latents (one warp per row, per-row scale)
// ---------------------------------------------------------------------------
__global__ __launch_bounds__(256) void k_quant_x(const float* __restrict__ lat) {
    const int tid = threadIdx.x, lane = tid & 31, w = tid >> 5;
    const int row = blockIdx.x * 8 + w;
    const float4* xr = (const float4*)(lat + (size_t)row * DDIM);
    float4 a = xr[lane * 2], b = xr[lane * 2 + 1];
    float mx = fmaxf(fmaxf(fmaxf(fabsf(a.x), fabsf(a.y)), fmaxf(fabsf(a.z), fabsf(a.w))),
                     fmaxf(fmaxf(fabsf(b.x), fabsf(b.y)), fmaxf(fabsf(b.z), fabsf(b.w))));
#pragma unroll
    for (int o = 16; o; o >>= 1) mx = fmaxf(mx, __shfl_xor_sync(0xffffffffu, mx, o));
    float sx = fmaxf(mx, 1e-20f) / 127.f;
    float inv = 127.f / fmaxf(mx, 1e-20f);
    int w0 = pack4(q8(a.x * inv), q8(a.y * inv), q8(a.z * inv), q8(a.w * inv));
    int w1 = pack4(q8(b.x * inv), q8(b.y * inv), q8(b.z * inv), q8(b.w * inv));
    ((int2*)(d_xq + (size_t)row * NW))[lane] = make_int2(w0, w1);
    if (lane == 0) {
        d_sx[row]   = sx;
        d_epsi[row] = (int)(EPSF / (sx * (1.0f / SC_INV))) + 1;
    }
}

// ---------------------------------------------------------------------------
// Kernel 2b: quantize codebook (global scale sc = 1/(8192*127))
// ---------------------------------------------------------------------------
__global__ __launch_bounds__(256) void k_quant_c(const float* __restrict__ cb) {
    int g = blockIdx.x * 256 + threadIdx.x;     // one int32 word (4 floats)
    float4 v = ((const float4*)cb)[g];
    d_cq[g] = pack4(q8(v.x * SC_INV), q8(v.y * SC_INV), q8(v.z * SC_INV), q8(v.w * SC_INV));
}

// ---------------------------------------------------------------------------
// Kernel 3: persistent work-queue int8/dp4a scan
// unit = (rowblk of 128 rows) x (1024-code slice); 256 threads, 2 CTAs/SM
// ---------------------------------------------------------------------------
__global__ __launch_bounds__(256, 2) void k_scan_i8() {
    extern __shared__ __align__(16) int smi[];
    int* As = smi;                         // [w][row] stride 132
    int* Bs = smi + AW2;                   // 2 buffers x 4 sub [64][17]
    int* Rb = smi + AW2 + 2 * BBUF;        // [128] running max (int)

    const int tid = threadIdx.x;
    const int tx = tid & 15, ty = tid >> 4;
    __shared__ int s_unit;

    int cur_rb = -1;
    int epr[8];                            // per-row eps (this thread's 8 rows)

    for (;;) {
        if (tid == 0) s_unit = atomicAdd(&d_wq, 1);
        __syncthreads();
        const int u = s_unit;
        if (u >= NUNITS) break;
        const int rbi = u >> 3, ksl = u & 7;
        const int rowblk = rbi * TM;

        if (rbi != cur_rb) {
            __syncthreads();               // old Rb readers done (prev unit epilogue)
            if (tid < TM) Rb[tid] = -2147483647;
#pragma unroll
            for (int i = 0; i < 8; i++) {
                int s2 = tid + i * 256;
                int row = s2 >> 4, wq = s2 & 15;
                int4 v = *(const int4*)(d_xq + (size_t)(rowblk + row) * NW + wq * 4);
                As[(4 * wq + 0) * 132 + row] = v.x;
                As[(4 * wq + 1) * 132 + row] = v.y;
                As[(4 * wq + 2) * 132 + row] = v.z;
                As[(4 * wq + 3) * 132 + row] = v.w;
            }
#pragma unroll
            for (int rr = 0; rr < 8; rr++) epr[rr] = d_epsi[rowblk + 8 * ty + rr];
            cur_rb = rbi;
            __syncthreads();
        }

        const int* cqS = d_cq + (size_t)(ksl * KSLICE) * NW;

        // prologue: tile 0 -> buffer 0
        int4 pf[4];
#pragma unroll
        for (int i = 0; i < 4; i++) {
            int s2 = tid + i * 256;
            int col = s2 >> 4, wq = s2 & 15;
            pf[i] = *(const int4*)(cqS + (size_t)col * NW + wq * 4);
        }
#pragma unroll
        for (int i = 0; i < 4; i++) {
            int s2 = tid + i * 256;
            int col = s2 >> 4, wq = s2 & 15;
            int* dst = Bs + (col & 3) * BW2 + (col >> 2);
            dst[(4 * wq + 0) * 17] = pf[i].x;
            dst[(4 * wq + 1) * 17] = pf[i].y;
            dst[(4 * wq + 2) * 17] = pf[i].z;
            dst[(4 * wq + 3) * 17] = pf[i].w;
        }
        __syncthreads();

        for (int t = 0; t < TILES_PER_UNIT; t++) {
            int* Bcur = Bs + (t & 1) * BBUF;
            int* Bnxt = Bs + ((t & 1) ^ 1) * BBUF;

            // prefetch next tile's B into registers
            if (t + 1 < TILES_PER_UNIT) {
                const int* gB = cqS + (size_t)(t + 1) * TKT * NW;
#pragma unroll
                for (int i = 0; i < 4; i++) {
                    int s2 = tid + i * 256;
                    int col = s2 >> 4, wq = s2 & 15;
                    pf[i] = *(const int4*)(gB + (size_t)col * NW + wq * 4);
                }
            }

            // compute: 64 word-steps, 8 rows x 4 cols per thread
            int acc[8][4];
#pragma unroll
            for (int r = 0; r < 8; r++)
#pragma unroll
                for (int j = 0; j < 4; j++) acc[r][j] = 0;

#pragma unroll 4
            for (int w = 0; w < NW; w++) {
                const int* ap = As + w * 132 + 8 * ty;
                int4 a0 = *(const int4*)ap;
                int4 a1 = *(const int4*)(ap + 4);
                int bw[4];
#pragma unroll
                for (int j = 0; j < 4; j++) bw[j] = Bcur[j * BW2 + w * 17 + tx];
#pragma unroll
                for (int j = 0; j < 4; j++) {
                    acc[0][j] = dp4a(acc[0][j], a0.x, bw[j]);
                    acc[1][j] = dp4a(acc[1][j], a0.y, bw[j]);
                    acc[2][j] = dp4a(acc[2][j], a0.z, bw[j]);
                    acc[3][j] = dp4a(acc[3][j], a0.w, bw[j]);
                    acc[4][j] = dp4a(acc[4][j], a1.x, bw[j]);
                    acc[5][j] = dp4a(acc[5][j], a1.y, bw[j]);
                    acc[6][j] = dp4a(acc[6][j], a1.z, bw[j]);
                    acc[7][j] = dp4a(acc[7][j], a1.w, bw[j]);
                }
            }

            // store prefetched tile into other buffer
            if (t + 1 < TILES_PER_UNIT) {
#pragma unroll
                for (int i = 0; i < 4; i++) {
                    int s2 = tid + i * 256;
                    int col = s2 >> 4, wq = s2 & 15;
                    int* dst = Bnxt + (col & 3) * BW2 + (col >> 2);
                    dst[(4 * wq + 0) * 17] = pf[i].x;
                    dst[(4 * wq + 1) * 17] = pf[i].y;
                    dst[(4 * wq + 2) * 17] = pf[i].z;
                    dst[(4 * wq + 3) * 17] = pf[i].w;
                }
            }

            // epilogue: running max + collect (stale Rb only over-collects)
            const int kbase = ksl * KSLICE + t * TKT;
#pragma unroll
            for (int rr = 0; rr < 8; rr++) {
                int m = max(max(acc[rr][0], acc[rr][1]), max(acc[rr][2], acc[rr][3]));
                m = max(m, __shfl_xor_sync(0xffffffffu, m, 1));
                m = max(m, __shfl_xor_sync(0xffffffffu, m, 2));
                m = max(m, __shfl_xor_sync(0xffffffffu, m, 4));
                m = max(m, __shfl_xor_sync(0xffffffffu, m, 8));
                if (tx == 0) {
                    if (m > Rb[8 * ty + rr]) atomicMax(&Rb[8 * ty + rr], m);
                }
            }
#pragma unroll
            for (int rr = 0; rr < 8; rr++) {
                const int thr = Rb[8 * ty + rr] - epr[rr];
                const int grow = rowblk + 8 * ty + rr;
#pragma unroll
                for (int j = 0; j < 4; j++) {
                    if (acc[rr][j] > thr) {
                        int pos = atomicAdd(&d_cnt[grow], 1);
                        if (pos < SLOTS)
                            d_cand[grow * SLOTS + pos] = kbase + 4 * tx + j;
                    }
                }
            }
            __syncthreads();
        }
    }
}

// ---------------------------------------------------------------------------
// Kernel 4: exact re-evaluation of candidates, replicate reference rounding:
// q = fl( fl(xn2 + cn2) - 2*dot_f ), argmin with lowest-index ties.
// ---------------------------------------------------------------------------
__global__ __launch_bounds__(256) void k_exact(const float* __restrict__ lat,
                                               const float* __restrict__ cb,
                                               float* __restrict__ out) {
    const int tid = threadIdx.x;
    const int lane = tid & 31, w = tid >> 5;
    const int row = blockIdx.x * 8 + w;

    float x[8];
    {
        const float4* xr = (const float4*)(lat + (size_t)row * DDIM);
        float4 a = xr[lane * 2], b = xr[lane * 2 + 1];
        x[0]=a.x; x[1]=a.y; x[2]=a.z; x[3]=a.w;
        x[4]=b.x; x[5]=b.y; x[6]=b.z; x[7]=b.w;
    }
    double xs = 0.0;
#pragma unroll
    for (int i = 0; i < 8; i++) xs += (double)x[i] * (double)x[i];
#pragma unroll
    for (int o = 16; o; o >>= 1) xs += __shfl_xor_sync(0xffffffffu, xs, o);
    float xn2 = (float)xs;

    int   n     = d_cnt[row];
    bool  fallb = (n > SLOTS);
    int   ncand = fallb ? KCB : n;

    float bestq = 3.4e38f;
    int   besti = 0;

    for (int c = 0; c < ncand; c++) {
        int idx = fallb ? c : d_cand[row * SLOTS + c];
        const float4* cr = (const float4*)(cb + (size_t)idx * DDIM);
        float4 a = cr[lane * 2], b = cr[lane * 2 + 1];
        float cv[8] = {a.x, a.y, a.z, a.w, b.x, b.y, b.z, b.w};

        float hi = 0.f, co = 0.f, cn = 0.f;
#pragma unroll
        for (int i = 0; i < 8; i++) {
            float p = __fmul_rn(x[i], cv[i]);
            float e = __fmaf_rn(x[i], cv[i], -p);
            float t = __fadd_rn(hi, p);
            float z = __fsub_rn(t, hi);
            float q2 = __fadd_rn(__fsub_rn(hi, __fsub_rn(t, z)), __fsub_rn(p, z));
            hi = t; co = __fadd_rn(co, __fadd_rn(q2, e));
            cn = __fmaf_rn(cv[i], cv[i], cn);
        }
#pragma unroll
        for (int o = 16; o; o >>= 1) {
            float h2 = __shfl_xor_sync(0xffffffffu, hi, o);
            float c2 = __shfl_xor_sync(0xffffffffu, co, o);
            cn += __shfl_xor_sync(0xffffffffu, cn, o);
            float t = __fadd_rn(hi, h2);
            float z = __fsub_rn(t, hi);
            float q2 = __fadd_rn(__fsub_rn(hi, __fsub_rn(t, z)), __fsub_rn(h2, z));
            hi = t; co = __fadd_rn(co, __fadd_rn(c2, q2));
        }
        if (lane == 0) {
            float df = __fadd_rn(hi, co);
            float t1 = __fadd_rn(xn2, cn);
            float q  = __fadd_rn(t1, -__fmul_rn(2.f, df));
            if (q < bestq || (q == bestq && idx < besti)) { bestq = q; besti = idx; }
        }
    }
    if (lane == 0) {
        d_bidx[row] = besti;
        out[row] = (float)besti;
    }
}

// ---------------------------------------------------------------------------
// Kernel 5: gather -> quantized + st_quantized, MSE partials, histogram
// ---------------------------------------------------------------------------
__global__ __launch_bounds__(256) void k_gather(const float* __restrict__ lat,
                                                const float* __restrict__ mask,
                                                const float* __restrict__ cb,
                                                float* __restrict__ out) {
    __shared__ float wsum[8];
    const int tid = threadIdx.x;
    const int lane = tid & 31, w = tid >> 5;
    const int row = blockIdx.x * 8 + w;

    int idx = d_bidx[row];
    const float4* x = (const float4*)(lat + (size_t)row * DDIM);
    const float4* c = (const float4*)(cb + (size_t)idx * DDIM);
    float4* q  = (float4*)(out + OFF_Q  + (size_t)row * DDIM);
    float4* st = (float4*)(out + OFF_ST + (size_t)row * DDIM);

    float s = 0.f;
#pragma unroll
    for (int i = lane; i < DDIM / 4; i += 32) {
        float4 cv = c[i], xv = x[i];
        q[i]  = cv;
        st[i] = cv;
        float d0 = xv.x - cv.x, d1 = xv.y - cv.y;
        float d2 = xv.z - cv.z, d3 = xv.w - cv.w;
        s += d0 * d0 + d1 * d1 + d2 * d2 + d3 * d3;
    }
#pragma unroll
    for (int o = 16; o; o >>= 1) s += __shfl_xor_sync(0xffffffffu, s, o);
    if (lane == 0) {
        wsum[w] = s;
        atomicAdd(&d_hist[idx], mask[row]);
    }
    __syncthreads();
    if (tid == 0) {
        double t = 0.0;
#pragma unroll
        for (int i = 0; i < 8; i++) t += (double)wsum[i];
        atomicAdd(&d_sqsum, t);
    }
}

// ---------------------------------------------------------------------------
// Kernel 6: finalize losses + perplexity
// ---------------------------------------------------------------------------
__global__ void k_final(const float* __restrict__ mask, float* __restrict__ out) {
    __shared__ float sh[256];
    const int tid = threadIdx.x;

    float m = 0.f;
    for (int i = tid; i < NROWS; i += 256) m += mask[i];
    sh[tid] = m; __syncthreads();
    for (int o = 128; o; o >>= 1) { if (tid < o) sh[tid] += sh[tid + o]; __syncthreads(); }
    float denom = fmaxf(sh[0], 1.0f);
    __syncthreads();

    float e = 0.f;
    for (int k2 = tid; k2 < KCB; k2 += 256) {
        float p = d_hist[k2] / denom;
        e += p * logf(p + 1e-8f);
    }
    sh[tid] = e; __syncthreads();
    for (int o = 128; o; o >>= 1) { if (tid < o) sh[tid] += sh[tid + o]; __syncthreads(); }

    if (tid == 0) {
        double mse = d_sqsum / (double)((size_t)NROWS * DDIM);
        out[OFF_SC + 0] = (float)(mse * 0.25);
        out[OFF_SC + 1] = (float)mse;
        out[OFF_SC + 2] = expf(-sh[0]);
    }
}

// ---------------------------------------------------------------------------
extern "C" void kernel_launch(void* const* d_in, const int* in_sizes, int n_in,
                              void* d_out, int out_size) {
    const float* lat  = (const float*)d_in[0];
    const float* mask = (const float*)d_in[1];
    const float* cb   = (const float*)d_in[2];
    float* out = (float*)d_out;

    cudaFuncSetAttribute(k_scan_i8, cudaFuncAttributeMaxDynamicSharedMemorySize, SMEM_BYTES);

    k_init   <<<NROWS / 256, 256>>>();
    k_quant_x<<<NROWS / 8, 256>>>(lat);
    k_quant_c<<<KCB * NW / 256, 256>>>(cb);
    k_scan_i8<<<GRID_SCAN, 256, SMEM_BYTES>>>();
    k_exact  <<<NROWS / 8, 256>>>(lat, cb, out);
    k_gather <<<NROWS / 8, 256>>>(lat, mask, cb, out);
    k_final  <<<1, 256>>>(mask, out);
}

// round 8
// speedup vs baseline: 2.3931x; 2.3931x over previous
#include <cuda_runtime.h>
#include <cuda_fp16.h>
#include <math.h>
#include <stdint.h>

#define NROWS 16384
#define DDIM  256
#define KCB   8192
#define NRB   128                 // rowblks
#define TM    128

#define OFF_Q   16384
#define OFF_ST  (16384 + NROWS*DDIM)
#define OFF_SC  (16384 + 2*NROWS*DDIM)

#define SLOTS 64
#define EPSF  2e-4f

#define TKT 128                   // codebook cols per tile
#define DC  64                    // d per stage
#define KSLICE 1024
#define NSL 8
#define NUNITS (NRB * NSL)        // 1024
#define USTAGES 32                // 8 tiles x 4 stages
#define GRID_SCAN 148

#define AS_STRIDE 68
#define AW3 (DDIM * AS_STRIDE)    // 17408 words
#define BW3 (DC * TKT)            // 8192 words per buffer
#define SMEM_WORDS (AW3 + 3 * BW3 + TM + 16)
#define SMEM_BYTES (SMEM_WORDS * 4)   // 168,512 B

__device__ unsigned d_xt[(size_t)NRB * DDIM * 64];  // [rbi][d][rowpair] half2 (2 rows)
__device__ unsigned d_ct[(size_t)DDIM * KCB];       // [d][col] dup half2
__device__ float  d_epsp[NROWS];
__device__ float  d_hist[KCB];
__device__ int    d_bidx[NROWS];
__device__ int    d_cnt[NROWS];
__device__ int    d_cand[NROWS * SLOTS];
__device__ double d_sqsum;
__device__ int    d_wq;

// ---------------------------------------------------------------------------
// helpers
// ---------------------------------------------------------------------------
__device__ __forceinline__ uint32_t smem_u32(const void* p) {
    uint32_t a;
    asm("{ .reg .u64 t; cvta.to.shared.u64 t, %1; cvt.u32.u64 %0, t; }" : "=r"(a) : "l"(p));
    return a;
}
__device__ __forceinline__ void cp_async16(uint32_t dst, const void* src) {
    asm volatile("cp.async.cg.shared.global [%0], [%1], 16;" :: "r"(dst), "l"(src) : "memory");
}
#define CP_COMMIT() asm volatile("cp.async.commit_group;" ::: "memory")
#define CP_WAIT(n)  asm volatile("cp.async.wait_group %0;" :: "n"(n) : "memory")

__device__ __forceinline__ int   fmap(float f)  { int i = __float_as_int(f); return i < 0 ? i ^ 0x7FFFFFFF : i; }
__device__ __forceinline__ float funmap(int u)  { if (u < 0) u ^= 0x7FFFFFFF; return __int_as_float(u); }

// ---------------------------------------------------------------------------
// Kernel 1: zero accumulators + work queue
// ---------------------------------------------------------------------------
__global__ void k_init() {
    int i = blockIdx.x * 256 + threadIdx.x;
    if (i < KCB)   d_hist[i] = 0.f;
    if (i < NROWS) d_cnt[i]  = 0;
    if (i == 0)  { d_sqsum   = 0.0; d_wq = 0; }
}

// ---------------------------------------------------------------------------
// Kernel 2a: latents -> fp16, per-row scale, transposed [rbi][d][rowpair]
// ---------------------------------------------------------------------------
__global__ __launch_bounds__(256) void k_quant_x(const float* __restrict__ lat) {
    const int tid = threadIdx.x, lane = tid & 31, w = tid >> 5;
    const int row = blockIdx.x * 8 + w;
    const float4* xr = (const float4*)(lat + (size_t)row * DDIM);
    float4 a = xr[lane * 2], b = xr[lane * 2 + 1];
    float v[8] = {a.x, a.y, a.z, a.w, b.x, b.y, b.z, b.w};
    float mx = 0.f;
#pragma unroll
    for (int i = 0; i < 8; i++) mx = fmaxf(mx, fabsf(v[i]));
#pragma unroll
    for (int o = 16; o; o >>= 1) mx = fmaxf(mx, __shfl_xor_sync(0xffffffffu, mx, o));
    float inv = 1.f / fmaxf(mx, 1e-20f);

    unsigned short* xt16 = (unsigned short*)d_xt;
    const int rbi = row >> 7, rp = (row & 127) >> 1, par = row & 1;
#pragma unroll
    for (int i = 0; i < 8; i++) {
        int d = lane * 8 + i;
        xt16[(((size_t)rbi * DDIM + d) * 64 + rp) * 2 + par] =
            __half_as_ushort(__float2half_rn(v[i] * inv));
    }
    if (lane == 0) d_epsp[row] = EPSF * 8192.f * inv;
}

// ---------------------------------------------------------------------------
// Kernel 2b: codebook -> fp16 dup-half2, transposed [d][col] (coalesced writes)
// ---------------------------------------------------------------------------
__global__ __launch_bounds__(256) void k_quant_c(const float* __restrict__ cb) {
    int g = blockIdx.x * 256 + threadIdx.x;       // 2M elements
    int col = g & (KCB - 1), d = g >> 13;
    __half h = __float2half_rn(cb[(size_t)col * DDIM + d] * 8192.f);
    __half2 h2 = __halves2half2(h, h);
    d_ct[(size_t)d * KCB + col] = *(unsigned*)&h2;
}

// ---------------------------------------------------------------------------
// Kernel 3: persistent work-queue HFMA2 scan
// unit = (128-row block) x (1024-code slice); 256 threads, 1 CTA/SM
// thread tile: 8 rows (4 half2 pairs) x 8 cols
// ---------------------------------------------------------------------------
#define ISSUE_B(s_) do {                                                        \
    int kt_ = (s_) >> 2, c_ = (s_) & 3, buf_ = (s_) % 3;                        \
    const unsigned* gB_ = d_ct + (size_t)(c_ * DC) * KCB + ksl * KSLICE + kt_ * TKT; \
    _Pragma("unroll")                                                           \
    for (int i_ = 0; i_ < 8; i_++) {                                            \
        int s2_ = tid + i_ * 256;                                               \
        int dd_ = s2_ >> 5, ch_ = s2_ & 31;                                     \
        cp_async16(sbB + (uint32_t)(buf_ * BW3 + dd_ * TKT + ch_ * 4) * 4,      \
                   gB_ + (size_t)dd_ * KCB + ch_ * 4);                          \
    }                                                                           \
    CP_COMMIT();                                                                \
} while (0)

__global__ __launch_bounds__(256, 1) void k_scan_h2() {
    extern __shared__ __align__(16) unsigned smu[];
    unsigned* As = smu;
    unsigned* Bs = smu + AW3;
    int* Rb = (int*)(smu + AW3 + 3 * BW3);
    __shared__ int s_unit;

    const int tid = threadIdx.x;
    const int tx = tid & 15, ty = tid >> 4;
    const uint32_t sbA = smem_u32(As);
    const uint32_t sbB = smem_u32(Bs);

    int cur_rb = -1;
    float epr[8];

    for (;;) {
        if (tid == 0) s_unit = atomicAdd(&d_wq, 1);
        __syncthreads();                   // also fences prev unit's Rb readers
        const int u = s_unit;
        if (u >= NUNITS) break;
        const int rbi = u >> 3, ksl = u & 7;
        const int rowblk = rbi * TM;

        if (rbi != cur_rb) {
            const unsigned* gA = d_xt + (size_t)rbi * (DDIM * 64);
#pragma unroll
            for (int i = 0; i < 16; i++) {
                int s2 = tid + i * 256;
                int d = s2 >> 4, rpg = s2 & 15;
                cp_async16(sbA + (uint32_t)(d * AS_STRIDE + rpg * 4) * 4,
                           gA + (size_t)d * 64 + rpg * 4);
            }
            CP_COMMIT();
            if (tid < TM) Rb[tid] = fmap(-3.0e38f);
#pragma unroll
            for (int rr = 0; rr < 8; rr++) epr[rr] = d_epsp[rowblk + ty * 8 + rr];
            cur_rb = rbi;
        }

        ISSUE_B(0);
        ISSUE_B(1);

        float accf[8][8];
#pragma unroll
        for (int r = 0; r < 8; r++)
#pragma unroll
            for (int j = 0; j < 8; j++) accf[r][j] = 0.f;

        for (int s = 0; s < USTAGES; s++) {
            const int c = s & 3;
            const unsigned* B = Bs + (s % 3) * BW3;
            if (s + 2 < USTAGES) { CP_WAIT(1); } else { CP_WAIT(0); }
            __syncthreads();               // stage s resident; all warps done with buf (s+2)%3
            if (s + 2 < USTAGES) ISSUE_B(s + 2);

            __half2 acc[4][8];
#pragma unroll
            for (int p = 0; p < 4; p++)
#pragma unroll
                for (int j = 0; j < 8; j++) acc[p][j] = __float2half2_rn(0.f);

#pragma unroll 8
            for (int dd = 0; dd < DC; dd++) {
                uint4 av = *(const uint4*)(As + (size_t)(c * DC + dd) * AS_STRIDE + ty * 4);
                __half2 a0 = *(__half2*)&av.x, a1 = *(__half2*)&av.y;
                __half2 a2 = *(__half2*)&av.z, a3 = *(__half2*)&av.w;
#pragma unroll
                for (int j = 0; j < 8; j++) {
                    unsigned bw = B[dd * TKT + 16 * j + tx];
                    __half2 b = *(__half2*)&bw;
                    acc[0][j] = __hfma2(a0, b, acc[0][j]);
                    acc[1][j] = __hfma2(a1, b, acc[1][j]);
                    acc[2][j] = __hfma2(a2, b, acc[2][j]);
                    acc[3][j] = __hfma2(a3, b, acc[3][j]);
                }
            }
            // fold fp16 partials into fp32 master accumulators
#pragma unroll
            for (int p = 0; p < 4; p++)
#pragma unroll
                for (int j = 0; j < 8; j++) {
                    float2 f = __half22float2(acc[p][j]);
                    accf[2 * p + 0][j] += f.x;
                    accf[2 * p + 1][j] += f.y;
                }

            if (c == 3) {   // end of 128-col k-tile: running max + collect
                const int kbase = ksl * KSLICE + (s >> 2) * TKT;
#pragma unroll
                for (int rr = 0; rr < 8; rr++) {
                    float mx = accf[rr][0];
#pragma unroll
                    for (int j = 1; j < 8; j++) mx = fmaxf(mx, accf[rr][j]);
                    mx = fmaxf(mx, __shfl_xor_sync(0xffffffffu, mx, 1));
                    mx = fmaxf(mx, __shfl_xor_sync(0xffffffffu, mx, 2));
                    mx = fmaxf(mx, __shfl_xor_sync(0xffffffffu, mx, 4));
                    mx = fmaxf(mx, __shfl_xor_sync(0xffffffffu, mx, 8));
                    if (tx == 0) {
                        int mm = fmap(mx);
                        if (mm > Rb[ty * 8 + rr]) atomicMax(&Rb[ty * 8 + rr], mm);
                    }
                }
                // stale Rb reads only over-collect; argmax always collected (Rb <= true max)
#pragma unroll
                for (int rr = 0; rr < 8; rr++) {
                    const float thr = funmap(Rb[ty * 8 + rr]) - epr[rr];
                    const int grow = rowblk + ty * 8 + rr;
#pragma unroll
                    for (int j = 0; j < 8; j++) {
                        if (accf[rr][j] > thr) {
                            int pos = atomicAdd(&d_cnt[grow], 1);
                            if (pos < SLOTS)
                                d_cand[grow * SLOTS + pos] = kbase + 16 * j + tx;
                        }
                        accf[rr][j] = 0.f;
                    }
                }
            }
        }
    }
}

// ---------------------------------------------------------------------------
// Kernel 4: exact re-evaluation of candidates, replicate reference rounding:
// q = fl( fl(xn2 + cn2) - 2*dot_f ), argmin with lowest-index ties.
// ---------------------------------------------------------------------------
__global__ __launch_bounds__(256) void k_exact(const float* __restrict__ lat,
                                               const float* __restrict__ cb,
                                               float* __restrict__ out) {
    const int tid = threadIdx.x;
    const int lane = tid & 31, w = tid >> 5;
    const int row = blockIdx.x * 8 + w;

    float x[8];
    {
        const float4* xr = (const float4*)(lat + (size_t)row * DDIM);
        float4 a = xr[lane * 2], b = xr[lane * 2 + 1];
        x[0]=a.x; x[1]=a.y; x[2]=a.z; x[3]=a.w;
        x[4]=b.x; x[5]=b.y; x[6]=b.z; x[7]=b.w;
    }
    double xs = 0.0;
#pragma unroll
    for (int i = 0; i < 8; i++) xs += (double)x[i] * (double)x[i];
#pragma unroll
    for (int o = 16; o; o >>= 1) xs += __shfl_xor_sync(0xffffffffu, xs, o);
    float xn2 = (float)xs;

    int   n     = d_cnt[row];
    bool  fallb = (n > SLOTS);
    int   ncand = fallb ? KCB : n;

    float bestq = 3.4e38f;
    int   besti = 0;

    for (int c = 0; c < ncand; c++) {
        int idx = fallb ? c : d_cand[row * SLOTS + c];
        const float4* cr = (const float4*)(cb + (size_t)idx * DDIM);
        float4 a = cr[lane * 2], b = cr[lane * 2 + 1];
        float cv[8] = {a.x, a.y, a.z, a.w, b.x, b.y, b.z, b.w};

        float hi = 0.f, co = 0.f, cn = 0.f;
#pragma unroll
        for (int i = 0; i < 8; i++) {
            float p = __fmul_rn(x[i], cv[i]);
            float e = __fmaf_rn(x[i], cv[i], -p);
            float t = __fadd_rn(hi, p);
            float z = __fsub_rn(t, hi);
            float q2 = __fadd_rn(__fsub_rn(hi, __fsub_rn(t, z)), __fsub_rn(p, z));
            hi = t; co = __fadd_rn(co, __fadd_rn(q2, e));
            cn = __fmaf_rn(cv[i], cv[i], cn);
        }
#pragma unroll
        for (int o = 16; o; o >>= 1) {
            float h2 = __shfl_xor_sync(0xffffffffu, hi, o);
            float c2 = __shfl_xor_sync(0xffffffffu, co, o);
            cn += __shfl_xor_sync(0xffffffffu, cn, o);
            float t = __fadd_rn(hi, h2);
            float z = __fsub_rn(t, hi);
            float q2 = __fadd_rn(__fsub_rn(hi, __fsub_rn(t, z)), __fsub_rn(h2, z));
            hi = t; co = __fadd_rn(co, __fadd_rn(c2, q2));
        }
        if (lane == 0) {
            float df = __fadd_rn(hi, co);
            float t1 = __fadd_rn(xn2, cn);
            float q  = __fadd_rn(t1, -__fmul_rn(2.f, df));
            if (q < bestq || (q == bestq && idx < besti)) { bestq = q; besti = idx; }
        }
    }
    if (lane == 0) {
        d_bidx[row] = besti;
        out[row] = (float)besti;
    }
}

// ---------------------------------------------------------------------------
// Kernel 5: gather -> quantized + st_quantized, MSE partials, histogram
// ---------------------------------------------------------------------------
__global__ __launch_bounds__(256) void k_gather(const float* __restrict__ lat,
                                                const float* __restrict__ mask,
                                                const float* __restrict__ cb,
                                                float* __restrict__ out) {
    __shared__ float wsum[8];
    const int tid = threadIdx.x;
    const int lane = tid & 31, w = tid >> 5;
    const int row = blockIdx.x * 8 + w;

    int idx = d_bidx[row];
    const float4* x = (const float4*)(lat + (size_t)row * DDIM);
    const float4* c = (const float4*)(cb + (size_t)idx * DDIM);
    float4* q  = (float4*)(out + OFF_Q  + (size_t)row * DDIM);
    float4* st = (float4*)(out + OFF_ST + (size_t)row * DDIM);

    float s = 0.f;
#pragma unroll
    for (int i = lane; i < DDIM / 4; i += 32) {
        float4 cv = c[i], xv = x[i];
        q[i]  = cv;
        st[i] = cv;
        float d0 = xv.x - cv.x, d1 = xv.y - cv.y;
        float d2 = xv.z - cv.z, d3 = xv.w - cv.w;
        s += d0 * d0 + d1 * d1 + d2 * d2 + d3 * d3;
    }
#pragma unroll
    for (int o = 16; o; o >>= 1) s += __shfl_xor_sync(0xffffffffu, s, o);
    if (lane == 0) {
        wsum[w] = s;
        atomicAdd(&d_hist[idx], mask[row]);
    }
    __syncthreads();
    if (tid == 0) {
        double t = 0.0;
#pragma unroll
        for (int i = 0; i < 8; i++) t += (double)wsum[i];
        atomicAdd(&d_sqsum, t);
    }
}

// ---------------------------------------------------------------------------
// Kernel 6: finalize losses + perplexity
// ---------------------------------------------------------------------------
__global__ void k_final(const float* __restrict__ mask, float* __restrict__ out) {
    __shared__ float sh[256];
    const int tid = threadIdx.x;

    float m = 0.f;
    for (int i = tid; i < NROWS; i += 256) m += mask[i];
    sh[tid] = m; __syncthreads();
    for (int o = 128; o; o >>= 1) { if (tid < o) sh[tid] += sh[tid + o]; __syncthreads(); }
    float denom = fmaxf(sh[0], 1.0f);
    __syncthreads();

    float e = 0.f;
    for (int k2 = tid; k2 < KCB; k2 += 256) {
        float p = d_hist[k2] / denom;
        e += p * logf(p + 1e-8f);
    }
    sh[tid] = e; __syncthreads();
    for (int o = 128; o; o >>= 1) { if (tid < o) sh[tid] += sh[tid + o]; __syncthreads(); }

    if (tid == 0) {
        double mse = d_sqsum / (double)((size_t)NROWS * DDIM);
        out[OFF_SC + 0] = (float)(mse * 0.25);
        out[OFF_SC + 1] = (float)mse;
        out[OFF_SC + 2] = expf(-sh[0]);
    }
}

// ---------------------------------------------------------------------------
extern "C" void kernel_launch(void* const* d_in, const int* in_sizes, int n_in,
                              void* d_out, int out_size) {
    const float* lat  = (const float*)d_in[0];
    const float* mask = (const float*)d_in[1];
    const float* cb   = (const float*)d_in[2];
    float* out = (float*)d_out;

    cudaFuncSetAttribute(k_scan_h2, cudaFuncAttributeMaxDynamicSharedMemorySize, SMEM_BYTES);

    k_init   <<<NROWS / 256, 256>>>();
    k_quant_x<<<NROWS / 8, 256>>>(lat);
    k_quant_c<<<(DDIM * KCB) / 256, 256>>>(cb);
    k_scan_h2<<<GRID_SCAN, 256, SMEM_BYTES>>>();
    k_exact  <<<NROWS / 8, 256>>>(lat, cb, out);
    k_gather <<<NROWS / 8, 256>>>(lat, mask, cb, out);
    k_final  <<<1, 256>>>(mask, out);
}